// round 8
// baseline (speedup 1.0000x reference)
#include <cuda_runtime.h>
#include <cuda_fp16.h>

#define NN 50000
#define EE 1600000
#define F  128
#define H  4
#define D  32
#define HD 128

#define SCAN_BLK 256

// Scratch (allocation-free rule: __device__ globals)
__device__ __half g_h[NN * HD];         // projected features fp16, 12.8 MB (L2-resident)
__device__ float g_es[NN * H];          // per-node source logits
__device__ float g_ed[NN * H];          // per-node dest logits
__device__ int   g_count[NN];           // in-degree histogram
__device__ int   g_rowstart[NN + 1];    // CSR row offsets (by dst)
__device__ int   g_cursor[NN];          // scatter cursors
__device__ int   g_srcsorted[EE];       // src node per edge, grouped by dst
__device__ int   g_is64;                // 1 if edge arrays are int64, 0 if int32

__device__ __forceinline__ int edge_at(const void* edges, int i) {
    if (g_is64) return (int)((const long long*)edges)[i];
    return ((const int*)edges)[i];
}

// ---------------------------------------------------------------------------
// K0: zero the histogram + detect edge dtype
// ---------------------------------------------------------------------------
__global__ void zero_kernel(int n, const void* edges) {
    int i = blockIdx.x * blockDim.x + threadIdx.x;
    if (i < n) g_count[i] = 0;
    if (i == 0) {
        const long long* p = (const long long*)edges;
        int ok = 1;
        #pragma unroll
        for (int q = 0; q < 8; q++) {
            long long v = p[q];
            if (v < 0 || v >= NN) ok = 0;
        }
        g_is64 = ok;
    }
}

// ---------------------------------------------------------------------------
// K1: HYBRID kernel. Blocks [0, gemm_blocks): HMMA GEMM + fused logits.
//     Blocks [gemm_blocks, ...): in-degree histogram, 8 edges/thread.
// ---------------------------------------------------------------------------
__global__ __launch_bounds__(256) void gemm_hist_kernel(
    const float* __restrict__ x, const float* __restrict__ W,
    const float* __restrict__ a_src, const float* __restrict__ a_dst, int n,
    const void* __restrict__ edge_dst, int e, int gemm_blocks)
{
    __shared__ __half ws[128][136];    // [k][n], 272B row stride
    __shared__ float as_s[128];
    __shared__ float ad_s[128];

    int tid = threadIdx.x;

    if (blockIdx.x >= gemm_blocks) {
        // ----- histogram part: 8 edges per thread -----
        int hb = blockIdx.x - gemm_blocks;
        int i8 = (hb * 256 + tid) * 8;
        if (i8 + 7 < e) {
            int d[8];
            if (g_is64) {
                #pragma unroll
                for (int q = 0; q < 4; q++) {
                    longlong2 p = ((const longlong2*)edge_dst)[(i8 >> 1) + q];
                    d[q * 2]     = (int)p.x;
                    d[q * 2 + 1] = (int)p.y;
                }
            } else {
                int4 p0 = ((const int4*)edge_dst)[i8 >> 2];
                int4 p1 = ((const int4*)edge_dst)[(i8 >> 2) + 1];
                d[0] = p0.x; d[1] = p0.y; d[2] = p0.z; d[3] = p0.w;
                d[4] = p1.x; d[5] = p1.y; d[6] = p1.z; d[7] = p1.w;
            }
            #pragma unroll
            for (int q = 0; q < 8; q++) atomicAdd(&g_count[d[q]], 1);
        } else {
            for (int i = i8; i < e; i++) atomicAdd(&g_count[edge_at(edge_dst, i)], 1);
        }
        return;
    }

    // ----- GEMM part -----
    int warp = tid >> 5;
    int lane = tid & 31;

    {
        const float4* W4 = (const float4*)W;
        #pragma unroll
        for (int q = 0; q < 16; q++) {
            int linear = q * 256 + tid;
            int row = linear >> 5;
            int c4  = linear & 31;
            float4 v = W4[linear];
            *(__half2*)&ws[row][c4 * 4]     = __floats2half2_rn(v.x, v.y);
            *(__half2*)&ws[row][c4 * 4 + 2] = __floats2half2_rn(v.z, v.w);
        }
        if (tid < 128) as_s[tid] = a_src[tid];
        else           ad_s[tid - 128] = a_dst[tid - 128];
    }
    __syncthreads();

    int mbase = blockIdx.x * 128 + warp * 16;
    int r0 = mbase + (lane >> 2);
    int r1 = r0 + 8;
    int c0 = (lane & 3) * 2;
    bool v0 = r0 < n, v1 = r1 < n;

    float acc[16][4];
    #pragma unroll
    for (int j = 0; j < 16; j++)
        #pragma unroll
        for (int q = 0; q < 4; q++) acc[j][q] = 0.f;

    const float* xr0 = x + (size_t)(v0 ? r0 : 0) * 128;
    const float* xr1 = x + (size_t)(v1 ? r1 : 0) * 128;
    int brow = lane & 15;

    #pragma unroll
    for (int t = 0; t < 8; t++) {
        int cb = t * 16 + c0;
        float2 f00 = v0 ? *(const float2*)(xr0 + cb)     : make_float2(0.f, 0.f);
        float2 f01 = v0 ? *(const float2*)(xr0 + cb + 8) : make_float2(0.f, 0.f);
        float2 f10 = v1 ? *(const float2*)(xr1 + cb)     : make_float2(0.f, 0.f);
        float2 f11 = v1 ? *(const float2*)(xr1 + cb + 8) : make_float2(0.f, 0.f);

        __half2 ha0 = __floats2half2_rn(f00.x, f00.y);
        __half2 ha1 = __floats2half2_rn(f10.x, f10.y);
        __half2 ha2 = __floats2half2_rn(f01.x, f01.y);
        __half2 ha3 = __floats2half2_rn(f11.x, f11.y);
        unsigned a0 = *(unsigned*)&ha0;
        unsigned a1 = *(unsigned*)&ha1;
        unsigned a2 = *(unsigned*)&ha2;
        unsigned a3 = *(unsigned*)&ha3;

        #pragma unroll
        for (int j = 0; j < 16; j++) {
            unsigned b0, b1;
            unsigned baddr = (unsigned)__cvta_generic_to_shared(
                &ws[t * 16 + brow][j * 8]);
            asm volatile(
                "ldmatrix.sync.aligned.m8n8.x2.trans.shared.b16 {%0,%1}, [%2];"
                : "=r"(b0), "=r"(b1) : "r"(baddr));
            asm volatile(
                "mma.sync.aligned.m16n8k16.row.col.f32.f16.f16.f32 "
                "{%0,%1,%2,%3}, {%4,%5,%6,%7}, {%8,%9}, {%0,%1,%2,%3};"
                : "+f"(acc[j][0]), "+f"(acc[j][1]), "+f"(acc[j][2]), "+f"(acc[j][3])
                : "r"(a0), "r"(a1), "r"(a2), "r"(a3), "r"(b0), "r"(b1));
        }
    }

    if (v0) {
        #pragma unroll
        for (int j = 0; j < 16; j++)
            *(__half2*)&g_h[(size_t)r0 * HD + j * 8 + c0] =
                __floats2half2_rn(acc[j][0], acc[j][1]);
    }
    if (v1) {
        #pragma unroll
        for (int j = 0; j < 16; j++)
            *(__half2*)&g_h[(size_t)r1 * HD + j * 8 + c0] =
                __floats2half2_rn(acc[j][2], acc[j][3]);
    }

    // Fused logits
    float4 es0 = make_float4(0,0,0,0), ed0 = es0, es1 = es0, ed1 = es0;
    #pragma unroll
    for (int hd = 0; hd < 4; hd++) {
        float s0 = 0.f, d0 = 0.f, s1 = 0.f, d1 = 0.f;
        #pragma unroll
        for (int jj = 0; jj < 4; jj++) {
            int j = hd * 4 + jj;
            float wa = as_s[j * 8 + c0];
            float wb = as_s[j * 8 + c0 + 1];
            float va = ad_s[j * 8 + c0];
            float vb = ad_s[j * 8 + c0 + 1];
            s0 = fmaf(acc[j][0], wa, fmaf(acc[j][1], wb, s0));
            d0 = fmaf(acc[j][0], va, fmaf(acc[j][1], vb, d0));
            s1 = fmaf(acc[j][2], wa, fmaf(acc[j][3], wb, s1));
            d1 = fmaf(acc[j][2], va, fmaf(acc[j][3], vb, d1));
        }
        ((float*)&es0)[hd] = s0; ((float*)&ed0)[hd] = d0;
        ((float*)&es1)[hd] = s1; ((float*)&ed1)[hd] = d1;
    }
    #pragma unroll
    for (int off = 1; off <= 2; off <<= 1) {
        #pragma unroll
        for (int q = 0; q < 4; q++) {
            ((float*)&es0)[q] += __shfl_xor_sync(0xffffffffu, ((float*)&es0)[q], off);
            ((float*)&ed0)[q] += __shfl_xor_sync(0xffffffffu, ((float*)&ed0)[q], off);
            ((float*)&es1)[q] += __shfl_xor_sync(0xffffffffu, ((float*)&es1)[q], off);
            ((float*)&ed1)[q] += __shfl_xor_sync(0xffffffffu, ((float*)&ed1)[q], off);
        }
    }
    if ((lane & 3) == 0) {
        if (v0) {
            *(float4*)&g_es[r0 * H] = es0;
            *(float4*)&g_ed[r0 * H] = ed0;
        }
        if (v1) {
            *(float4*)&g_es[r1 * H] = es1;
            *(float4*)&g_ed[r1 * H] = ed1;
        }
    }
}

// ---------------------------------------------------------------------------
// K2: single-kernel scan. Each block redundantly reduces all PRIOR counts
// (coalesced, MLP-rich) for its offset, then local Hillis-Steele.
// ---------------------------------------------------------------------------
__global__ __launch_bounds__(SCAN_BLK) void scan_kernel(int n) {
    __shared__ int sh[SCAN_BLK];
    __shared__ int wred[8];
    int t = threadIdx.x;
    int base = blockIdx.x * SCAN_BLK;

    // offset = sum of counts[0 .. base)
    int pre = 0;
    #pragma unroll 4
    for (int i = t; i < base; i += SCAN_BLK) pre += g_count[i];
    #pragma unroll
    for (int off = 16; off >= 1; off >>= 1)
        pre += __shfl_down_sync(0xffffffffu, pre, off);
    if ((t & 31) == 0) wred[t >> 5] = pre;

    int i = base + t;
    int v = (i < n) ? g_count[i] : 0;
    sh[t] = v;
    __syncthreads();

    int boff = wred[0] + wred[1] + wred[2] + wred[3]
             + wred[4] + wred[5] + wred[6] + wred[7];

    #pragma unroll
    for (int off = 1; off < SCAN_BLK; off <<= 1) {
        int w = (t >= off) ? sh[t - off] : 0;
        __syncthreads();
        sh[t] += w;
        __syncthreads();
    }
    if (i < n) {
        int val = boff + sh[t] - v;  // exclusive prefix
        g_rowstart[i] = val;
        g_cursor[i]   = val;
    }
    if (blockIdx.x == gridDim.x - 1 && t == SCAN_BLK - 1)
        g_rowstart[n] = boff + sh[t];   // grand total (zero-padded tail is safe)
}

// ---------------------------------------------------------------------------
// K3: scatter edges into dst-grouped order, 8 edges per thread
// ---------------------------------------------------------------------------
__global__ void scatter_kernel(const void* __restrict__ edge_src,
                               const void* __restrict__ edge_dst, int e)
{
    int i8 = (blockIdx.x * blockDim.x + threadIdx.x) * 8;
    if (i8 + 7 < e) {
        int d[8], s[8];
        if (g_is64) {
            #pragma unroll
            for (int q = 0; q < 4; q++) {
                longlong2 p = ((const longlong2*)edge_dst)[(i8 >> 1) + q];
                d[q * 2] = (int)p.x; d[q * 2 + 1] = (int)p.y;
                longlong2 r = ((const longlong2*)edge_src)[(i8 >> 1) + q];
                s[q * 2] = (int)r.x; s[q * 2 + 1] = (int)r.y;
            }
        } else {
            int4 p0 = ((const int4*)edge_dst)[i8 >> 2];
            int4 p1 = ((const int4*)edge_dst)[(i8 >> 2) + 1];
            d[0] = p0.x; d[1] = p0.y; d[2] = p0.z; d[3] = p0.w;
            d[4] = p1.x; d[5] = p1.y; d[6] = p1.z; d[7] = p1.w;
            int4 q0 = ((const int4*)edge_src)[i8 >> 2];
            int4 q1 = ((const int4*)edge_src)[(i8 >> 2) + 1];
            s[0] = q0.x; s[1] = q0.y; s[2] = q0.z; s[3] = q0.w;
            s[4] = q1.x; s[5] = q1.y; s[6] = q1.z; s[7] = q1.w;
        }
        #pragma unroll
        for (int q = 0; q < 8; q++) {
            int pos = atomicAdd(&g_cursor[d[q]], 1);
            g_srcsorted[pos] = s[q];
        }
    } else {
        for (int i = i8; i < e; i++) {
            int dst = edge_at(edge_dst, i);
            int pos = atomicAdd(&g_cursor[dst], 1);
            g_srcsorted[pos] = edge_at(edge_src, i);
        }
    }
}

// ---------------------------------------------------------------------------
// K4: aggregation. One warp per destination node; TWO edges per iteration
// via 16-lane groups (uint4 row loads). fp32 accumulators, no output atomics.
// ---------------------------------------------------------------------------
__global__ void agg_kernel(const float* __restrict__ bias,
                           float* __restrict__ out, int n)
{
    int gw = (blockIdx.x * blockDim.x + threadIdx.x) >> 5;
    int lane = threadIdx.x & 31;
    if (gw >= n) return;
    int sl  = lane & 15;     // lane within group: features [8sl, 8sl+8)
    int grp = lane >> 4;     // 0: even edges, 1: odd edges
    int hd  = sl >> 2;       // head of this lane's features

    float edv = g_ed[gw * H + hd];
    int start = g_rowstart[gw];
    int end   = g_rowstart[gw + 1];

    float acc[8];
    #pragma unroll
    for (int q = 0; q < 8; q++) acc[q] = 0.f;
    float denom = 0.f;
    const uint4* h4 = (const uint4*)g_h;

    #pragma unroll 4
    for (int i = start + grp; i < end; i += 2) {
        int src = g_srcsorted[i];
        float ev = g_es[src * H + hd] + edv;
        ev = fmaxf(ev, 0.2f * ev);          // LeakyReLU(0.2)
        float al = __expf(ev);
        denom += al;
        uint4 raw = h4[(size_t)src * 16 + sl];
        __half2* hh = (__half2*)&raw;
        #pragma unroll
        for (int q = 0; q < 4; q++) {
            float2 f = __half22float2(hh[q]);
            acc[2 * q]     = fmaf(al, f.x, acc[2 * q]);
            acc[2 * q + 1] = fmaf(al, f.y, acc[2 * q + 1]);
        }
    }

    // combine the two edge-groups (lane l += lane l+16)
    denom += __shfl_down_sync(0xffffffffu, denom, 16);
    #pragma unroll
    for (int q = 0; q < 8; q++)
        acc[q] += __shfl_down_sync(0xffffffffu, acc[q], 16);

    if (grp == 0) {
        float inv = denom > 0.f ? 1.0f / denom : 0.f;
        float4 b0 = ((const float4*)bias)[sl * 2];
        float4 b1 = ((const float4*)bias)[sl * 2 + 1];
        float4 o0, o1;
        o0.x = fmaf(acc[0], inv, b0.x);
        o0.y = fmaf(acc[1], inv, b0.y);
        o0.z = fmaf(acc[2], inv, b0.z);
        o0.w = fmaf(acc[3], inv, b0.w);
        o1.x = fmaf(acc[4], inv, b1.x);
        o1.y = fmaf(acc[5], inv, b1.y);
        o1.z = fmaf(acc[6], inv, b1.z);
        o1.w = fmaf(acc[7], inv, b1.w);
        ((float4*)out)[(size_t)gw * 32 + sl * 2]     = o0;
        ((float4*)out)[(size_t)gw * 32 + sl * 2 + 1] = o1;
    }
}

// ---------------------------------------------------------------------------
extern "C" void kernel_launch(void* const* d_in, const int* in_sizes, int n_in,
                              void* d_out, int out_size)
{
    const float* x      = (const float*)d_in[0];
    const float* W      = (const float*)d_in[1];
    const float* a_src  = (const float*)d_in[2];
    const float* a_dst  = (const float*)d_in[3];
    const float* bias   = (const float*)d_in[4];
    const void*  esrc   = d_in[5];
    const void*  edst   = d_in[6];
    float* out = (float*)d_out;

    int n = in_sizes[0] / F;     // 50000
    int e = in_sizes[5];         // 1600000
    int nb = (n + SCAN_BLK - 1) / SCAN_BLK;

    int gemm_blocks = (n + 127) / 128;
    int hist_blocks = (e / 8 + 255) / 256;

    zero_kernel<<<(n + 255) / 256, 256>>>(n, edst);
    gemm_hist_kernel<<<gemm_blocks + hist_blocks, 256>>>(
        x, W, a_src, a_dst, n, edst, e, gemm_blocks);
    scan_kernel<<<nb, SCAN_BLK>>>(n);
    scatter_kernel<<<(e / 8 + 255) / 256, 256>>>(esrc, edst, e);
    agg_kernel<<<(n * 32 + 255) / 256, 256>>>(bias, out, n);
}